// round 16
// baseline (speedup 1.0000x reference)
#include <cuda_runtime.h>
#include <cuda_fp16.h>
#include <cstdint>
#include <cstddef>

// ---------------- problem constants ----------------
#define BDIM 8
#define EDIM 512
#define LDIM 8192
#define KSZ  5
#define LC   8188      // LDIM - KSZ + 1
#define TD   4096      // LDIM / 2
#define MBLK 128       // t tile
#define NBLK 256       // e tile
#define IBLK 16        // i (in-channel) per chunk
#define NCHI 32        // EDIM / IBLK

// smem geometry
#define A_STRIDE_B 272                 // 128 halves (256B) + 16B pad -> conflict-free trans ldmatrix
#define A_TILE     (IBLK * A_STRIDE_B) // 4352 B
#define A_SZ       (KSZ * A_TILE)      // 21760 B
#define B_STRIDE_B 48                  // 16 halves (32B) + 16B pad -> conflict-free ldmatrix
#define B_TILE     (NBLK * B_STRIDE_B) // 12288 B
#define B_SZ       (KSZ * B_TILE)      // 61440 B
#define BUF_B      (A_SZ + B_SZ)       // 83200 B
#define SMEM_TOTAL (2 * BUF_B)         // 166400 B

// ---------------- scratch (no allocations allowed) ----------------
__device__ __align__(16) __half g_yh[(size_t)BDIM * EDIM * LDIM];  // conv output (fp16)
__device__ float g_s[BDIM * LDIM];                          // score projection
__device__ float g_a1[BDIM * LDIM];                         // softmax weight w=1
__device__ float g_a2[BDIM * LDIM];                         // softmax weight w=2 (a3 = 1-a1-a2)
// 5 pre-shifted fp16 copies of x: g_xh5[k][b][i][t] = fp16(x[b][i][t+k]) (0 if OOB)
__device__ __align__(16) __half g_xh5[(size_t)KSZ * BDIM * EDIM * LDIM];
// fp16 weights: g_wk5[k][e][i] = fp16(W[e][i][k])
__device__ __align__(16) __half g_wk5[(size_t)KSZ * EDIM * EDIM];

// ---------------- PTX helpers (baseline ISA: sm_80-safe, compiles at compute_103) ----------------
__device__ __forceinline__ uint32_t smem_u32(const void* p) {
    uint32_t a;
    asm("{ .reg .u64 t; cvta.to.shared.u64 t, %1; cvt.u32.u64 %0, t; }" : "=r"(a) : "l"(p));
    return a;
}
__device__ __forceinline__ void ldsm_x4(uint32_t addr, uint32_t* r) {
    asm volatile("ldmatrix.sync.aligned.m8n8.x4.shared.b16 {%0,%1,%2,%3}, [%4];"
        : "=r"(r[0]), "=r"(r[1]), "=r"(r[2]), "=r"(r[3]) : "r"(addr));
}
__device__ __forceinline__ void ldsm_x4_t(uint32_t addr, uint32_t* r) {
    asm volatile("ldmatrix.sync.aligned.m8n8.x4.trans.shared.b16 {%0,%1,%2,%3}, [%4];"
        : "=r"(r[0]), "=r"(r[1]), "=r"(r[2]), "=r"(r[3]) : "r"(addr));
}
__device__ __forceinline__ void mma_fp16(float* d, const uint32_t* a, const uint32_t* b) {
    asm volatile("mma.sync.aligned.m16n8k16.row.col.f32.f16.f16.f32 "
        "{%0,%1,%2,%3}, {%4,%5,%6,%7}, {%8,%9}, {%0,%1,%2,%3};"
        : "+f"(d[0]), "+f"(d[1]), "+f"(d[2]), "+f"(d[3])
        : "r"(a[0]), "r"(a[1]), "r"(a[2]), "r"(a[3]), "r"(b[0]), "r"(b[1]));
}
__device__ __forceinline__ void cpa16(uint32_t dst, const void* src) {
    asm volatile("cp.async.cg.shared.global [%0], [%1], 16;" :: "r"(dst), "l"(src));
}
#define CP_COMMIT() asm volatile("cp.async.commit_group;" ::: "memory")
#define CP_WAIT(n)  asm volatile("cp.async.wait_group " #n ";" ::: "memory")

// ---------------- Kernel 0a: build 5 shifted fp16 copies of x ----------------
__global__ void prep_x_kernel(const float* __restrict__ x) {
    __shared__ __align__(16) float xs[2052];
    const int seg = blockIdx.x, i = blockIdx.y, b = blockIdx.z;
    const int t0 = seg * 2048;
    const int tid = threadIdx.x;
    const float* xr = x + ((size_t)b * EDIM + i) * LDIM + t0;

    const float4* xv = reinterpret_cast<const float4*>(xr);
    reinterpret_cast<float4*>(xs)[2 * tid]     = xv[2 * tid];
    reinterpret_cast<float4*>(xs)[2 * tid + 1] = xv[2 * tid + 1];
    if (tid < 4)
        xs[2048 + tid] = (t0 + 2048 + tid < LDIM) ? xr[2048 + tid] : 0.0f;
    __syncthreads();

    #pragma unroll
    for (int k = 0; k < KSZ; k++) {
        uint32_t p[4];
        #pragma unroll
        for (int q = 0; q < 4; q++) {
            __half2 h2 = __floats2half2_rn(xs[tid * 8 + k + 2 * q],
                                           xs[tid * 8 + k + 2 * q + 1]);
            p[q] = *reinterpret_cast<uint32_t*>(&h2);
        }
        __half* dst = g_xh5 + (((size_t)k * BDIM + b) * EDIM + i) * LDIM + t0 + tid * 8;
        *reinterpret_cast<uint4*>(dst) = make_uint4(p[0], p[1], p[2], p[3]);
    }
}

// ---------------- Kernel 0b: weights -> g_wk5[k][e][i] fp16; zero g_s ----------------
__global__ void prep_w_kernel(const float* __restrict__ w) {
    int idx = blockIdx.x * 256 + threadIdx.x;
    if (idx < KSZ * EDIM * EDIM) {
        int k = idx / (EDIM * EDIM);
        int r = idx - k * (EDIM * EDIM);
        int e = r / EDIM, i = r - e * EDIM;
        g_wk5[idx] = __float2half_rn(w[((size_t)e * EDIM + i) * KSZ + k]);
    }
    if (idx < BDIM * LDIM) g_s[idx] = 0.0f;
}

// ---------------- Kernel 1: conv as 5 shifted fp16 GEMMs (mma.sync) ----------------
// D[t,e] = sum_k sum_i g_xh5[k][b][i][t] * g_wk5[k][e][i]
// Block 128t x 256e, 512 threads (16 warps: 4m x 4n), chunks of 16 i, cp.async double buffer.
__global__ void __launch_bounds__(512, 1)
conv_mma_kernel(const float* __restrict__ cb,
                const float* __restrict__ sw) {
    extern __shared__ char smem[];
    const uint32_t sb = smem_u32(smem);
    const int tid = threadIdx.x;
    const int wid = tid >> 5, lid = tid & 31;
    const int b  = blockIdx.z;
    const int te = blockIdx.y * NBLK;
    const int tt = blockIdx.x * MBLK;

    float acc[2][8][4];
    #pragma unroll
    for (int i = 0; i < 2; i++)
        #pragma unroll
        for (int j = 0; j < 8; j++)
            #pragma unroll
            for (int q = 0; q < 4; q++)
                acc[i][j][q] = 0.0f;

    auto stage = [&](int c) {
        const int i0 = c * IBLK;
        const uint32_t bufb = sb + (c & 1) * BUF_B;
        // A: 5k x 16i x 16 t-vec16B = 1280 ops
        for (int o = tid; o < KSZ * IBLK * 16; o += 512) {
            int k = o >> 8;
            int r = o & 255;
            int i = r >> 4;
            int tc = r & 15;
            const __half* src = g_xh5 + (((size_t)k * BDIM + b) * EDIM + (i0 + i)) * LDIM
                              + tt + tc * 8;
            cpa16(bufb + k * A_TILE + i * A_STRIDE_B + tc * 16, src);
        }
        // B: 5k x 256e x 2 half-rows = 2560 ops
        for (int o = tid; o < KSZ * NBLK * 2; o += 512) {
            int k = o >> 9;
            int r = o & 511;
            int e = r >> 1;
            int h = r & 1;
            const __half* src = g_wk5 + ((size_t)k * EDIM + (te + e)) * EDIM + i0 + h * 8;
            cpa16(bufb + A_SZ + k * B_TILE + e * B_STRIDE_B + h * 16, src);
        }
    };

    const int wm = (wid & 3) * 32;     // warp m (t) offset
    const int wn = (wid >> 2) * 64;    // warp n (e) offset

    // A trans-ldmatrix lane addressing on [i][t] storage
    const uint32_t i_rowA = (uint32_t)((lid & 7) + ((lid & 16) ? 8 : 0));
    const uint32_t t_offA = (uint32_t)((lid & 8) ? 8 : 0);
    const uint32_t aoff   = i_rowA * A_STRIDE_B + (uint32_t)(wm + t_offA) * 2;
    // B non-trans, rows e of 16 i
    const int b_q   = lid >> 3;
    const int b_row = wn + ((b_q & 2) ? 8 : 0) + (lid & 7);
    const uint32_t b_cb = (uint32_t)((b_q & 1) ? 16 : 0);

    stage(0);
    CP_COMMIT();

    for (int c = 0; c < NCHI; c++) {
        if (c + 1 < NCHI) {
            stage(c + 1);
            CP_COMMIT();
            CP_WAIT(1);
        } else {
            CP_WAIT(0);
        }
        __syncthreads();

        const uint32_t bufb  = sb + (c & 1) * BUF_B;
        const uint32_t Bbase = bufb + A_SZ;
        #pragma unroll
        for (int k = 0; k < KSZ; k++) {
            const uint32_t Ak = bufb + k * A_TILE;
            const uint32_t Bk = Bbase + k * B_TILE;
            uint32_t a0[4], a1[4];
            ldsm_x4_t(Ak + aoff, a0);
            ldsm_x4_t(Ak + aoff + 32, a1);     // +16 t
            #pragma unroll
            for (int ng = 0; ng < 4; ng++) {
                uint32_t bb[4];
                ldsm_x4(Bk + (uint32_t)(b_row + ng * 16) * B_STRIDE_B + b_cb, bb);
                mma_fp16(acc[0][2 * ng],     a0, &bb[0]);
                mma_fp16(acc[0][2 * ng + 1], a0, &bb[2]);
                mma_fp16(acc[1][2 * ng],     a1, &bb[0]);
                mma_fp16(acc[1][2 * ng + 1], a1, &bb[2]);
            }
        }
        __syncthreads();
    }

    // ---- epilogue: bias + store y (fp16) + fused score projection ----
    // D fragment: c0:(t0,e0) c1:(t0,e0+1) c2:(t0+8,e0) c3:(t0+8,e0+1)
    const int r = lid & 3, qr = lid >> 2;
    #pragma unroll
    for (int mt = 0; mt < 2; mt++) {
        const int tg0 = tt + wm + mt * 16 + qr;   // and tg0 + 8
        float s0 = 0.0f, s1 = 0.0f;
        #pragma unroll
        for (int n8 = 0; n8 < 8; n8++) {
            const int e0 = te + wn + n8 * 8 + r * 2;
            const float cb0 = __ldg(&cb[e0]), cb1 = __ldg(&cb[e0 + 1]);
            const float sw0 = __ldg(&sw[e0]), sw1 = __ldg(&sw[e0 + 1]);
            float c0 = acc[mt][n8][0] + cb0;
            float c1 = acc[mt][n8][1] + cb1;
            float c2 = acc[mt][n8][2] + cb0;
            float c3 = acc[mt][n8][3] + cb1;
            __half* y0 = g_yh + ((size_t)b * EDIM + e0) * LDIM;
            __half* y1 = y0 + LDIM;
            if (tg0 < LC)     { y0[tg0] = __float2half_rn(c0);     y1[tg0] = __float2half_rn(c1); }
            if (tg0 + 8 < LC) { y0[tg0 + 8] = __float2half_rn(c2); y1[tg0 + 8] = __float2half_rn(c3); }
            s0 += c0 * sw0 + c1 * sw1;
            s1 += c2 * sw0 + c3 * sw1;
        }
        s0 += __shfl_xor_sync(0xFFFFFFFF, s0, 1);
        s0 += __shfl_xor_sync(0xFFFFFFFF, s0, 2);
        s1 += __shfl_xor_sync(0xFFFFFFFF, s1, 1);
        s1 += __shfl_xor_sync(0xFFFFFFFF, s1, 2);
        if (r == 0) {
            if (tg0 < LC)     atomicAdd(&g_s[b * LDIM + tg0], s0);
            if (tg0 + 8 < LC) atomicAdd(&g_s[b * LDIM + tg0 + 8], s1);
        }
    }
}

// ---------------- Kernel 2: per-(b,t) softmax over widths {1,2,3} ----------------
__global__ void att_kernel() {
    const int b = blockIdx.y;
    const int t = blockIdx.x * 256 + threadIdx.x;
    const float* s = g_s + b * LDIM;

    float sc1 = (t < LC) ? s[t] : 0.0f;
    int n2 = t >> 1;
    float sc2 = (t < LC) ? 0.5f * (s[2 * n2] + s[2 * n2 + 1]) : 0.0f;
    float sc3 = 0.0f;
    int m = t / 3;
    if (t < 8190) {
        sc3 = (s[3 * m] + s[3 * m + 1] + s[3 * m + 2]) * (1.0f / 3.0f);
    }
    float mx = fmaxf(sc1, fmaxf(sc2, sc3));
    float e1 = expf(sc1 - mx), e2 = expf(sc2 - mx), e3 = expf(sc3 - mx);
    float inv = 1.0f / (e1 + e2 + e3);
    g_a1[b * LDIM + t] = e1 * inv;
    g_a2[b * LDIM + t] = e2 * inv;
}

// ---------------- Kernel 3: mix widths + downsample by 2 (fp16 y, minimal L1 traffic) ----------------
__device__ __forceinline__ float v3_at(const __half* __restrict__ y, int t) {
    if (t >= 8190) return 0.0f;
    int i0 = 3 * (t / 3);                       // <= 8187, in-bounds
    float s0 = __half2float(y[i0]);
    float s1 = (i0 + 1 < LC) ? __half2float(y[i0 + 1]) : 0.0f;
    float s2 = (i0 + 2 < LC) ? __half2float(y[i0 + 2]) : 0.0f;
    return (s0 + s1 + s2) * (1.0f / 3.0f);
}

__global__ void final_kernel(float* __restrict__ out) {
    const int b  = blockIdx.z;
    const int e  = blockIdx.y;
    const int td = blockIdx.x * 256 + threadIdx.x;   // 0..4095
    const __half* y = g_yh + ((size_t)b * EDIM + e) * LDIM;
    const int t0 = 2 * td, t1 = t0 + 1;

    __half2 h01 = *reinterpret_cast<const __half2*>(y + t0);   // always in-bounds
    float v1_0 = (t0 < LC) ? __low2float(h01)  : 0.0f;
    float v1_1 = (t1 < LC) ? __high2float(h01) : 0.0f;
    float v2   = 0.5f * (v1_0 + v1_1);                         // shared w=2 block

    float v3_0 = v3_at(y, t0);
    float v3_1 = v3_at(y, t1);

    float2 a1 = *reinterpret_cast<const float2*>(g_a1 + b * LDIM + t0);
    float2 a2 = *reinterpret_cast<const float2*>(g_a2 + b * LDIM + t0);
    float a3_0 = 1.0f - a1.x - a2.x;
    float a3_1 = 1.0f - a1.y - a2.y;

    float z0 = v1_0 * a1.x + v2 * a2.x + v3_0 * a3_0;
    float z1 = v1_1 * a1.y + v2 * a2.y + v3_1 * a3_1;
    out[((size_t)b * EDIM + e) * TD + td] = 0.5f * (z0 + z1);
}

// ---------------- launch ----------------
extern "C" void kernel_launch(void* const* d_in, const int* in_sizes, int n_in,
                              void* d_out, int out_size) {
    (void)in_sizes; (void)n_in; (void)out_size;
    const float* x  = (const float*)d_in[0];   // [8,512,8192]
    const float* cw = (const float*)d_in[1];   // [512,512,5]
    const float* cb = (const float*)d_in[2];   // [512]
    const float* sw = (const float*)d_in[3];   // [512]
    float* out = (float*)d_out;                // [8,512,4096]

    cudaFuncSetAttribute(conv_mma_kernel,
                         cudaFuncAttributeMaxDynamicSharedMemorySize, SMEM_TOTAL);

    prep_x_kernel<<<dim3(LDIM / 2048, EDIM, BDIM), 256>>>(x);
    prep_w_kernel<<<(KSZ * EDIM * EDIM + 255) / 256, 256>>>(cw);
    conv_mma_kernel<<<dim3(LDIM / MBLK, EDIM / NBLK, BDIM), 512, SMEM_TOTAL>>>(cb, sw);
    att_kernel<<<dim3(LDIM / 256, BDIM), 256>>>();
    final_kernel<<<dim3(TD / 256, EDIM, BDIM), 256>>>(out);
}

// round 17
// speedup vs baseline: 1.4579x; 1.4579x over previous
#include <cuda_runtime.h>
#include <cuda_fp16.h>
#include <cstdint>
#include <cstddef>

// ---------------- problem constants ----------------
#define BDIM 8
#define EDIM 512
#define LDIM 8192
#define KSZ  5
#define LC   8188      // LDIM - KSZ + 1
#define TD   4096      // LDIM / 2
#define MBLK 128       // t tile
#define NBLK 256       // e tile
#define IBLK 16        // i (in-channel) per chunk
#define NCHI 32        // EDIM / IBLK

// smem geometry (R15-validated)
#define A_STRIDE_B 272                 // 128 halves (256B) + 16B pad -> conflict-free trans ldmatrix
#define A_TILE     (IBLK * A_STRIDE_B) // 4352 B
#define A_SZ       (KSZ * A_TILE)      // 21760 B
#define B_STRIDE_B 32                  // 16 halves per row
#define B_TILE     (NBLK * B_STRIDE_B) // 8192 B
#define B_SZ       (KSZ * B_TILE)      // 40960 B
#define BUF_B      (A_SZ + B_SZ)       // 62720 B
#define SMEM_TOTAL (2 * BUF_B)         // 125440 B

// ---------------- scratch (no allocations allowed) ----------------
__device__ float g_y[(size_t)BDIM * EDIM * LDIM];           // conv output (fp32)
__device__ float g_s[BDIM * LDIM];                          // score projection
__device__ float g_a1[BDIM * LDIM];                         // softmax weight w=1
__device__ float g_a2[BDIM * LDIM];                         // softmax weight w=2 (a3 = 1-a1-a2)
// 5 pre-shifted fp16 copies of x: g_xh5[k][b][i][t] = fp16(x[b][i][t+k]) (0 if OOB)
__device__ __align__(16) __half g_xh5[(size_t)KSZ * BDIM * EDIM * LDIM];
// fp16 weights: g_wk5[k][e][i] = fp16(W[e][i][k])
__device__ __align__(16) __half g_wk5[(size_t)KSZ * EDIM * EDIM];

// ---------------- PTX helpers (baseline ISA: sm_80-safe, compiles at compute_103) ----------------
__device__ __forceinline__ uint32_t smem_u32(const void* p) {
    uint32_t a;
    asm("{ .reg .u64 t; cvta.to.shared.u64 t, %1; cvt.u32.u64 %0, t; }" : "=r"(a) : "l"(p));
    return a;
}
__device__ __forceinline__ void ldsm_x4(uint32_t addr, uint32_t* r) {
    asm volatile("ldmatrix.sync.aligned.m8n8.x4.shared.b16 {%0,%1,%2,%3}, [%4];"
        : "=r"(r[0]), "=r"(r[1]), "=r"(r[2]), "=r"(r[3]) : "r"(addr));
}
__device__ __forceinline__ void ldsm_x4_t(uint32_t addr, uint32_t* r) {
    asm volatile("ldmatrix.sync.aligned.m8n8.x4.trans.shared.b16 {%0,%1,%2,%3}, [%4];"
        : "=r"(r[0]), "=r"(r[1]), "=r"(r[2]), "=r"(r[3]) : "r"(addr));
}
__device__ __forceinline__ void mma_fp16(float* d, const uint32_t* a, const uint32_t* b) {
    asm volatile("mma.sync.aligned.m16n8k16.row.col.f32.f16.f16.f32 "
        "{%0,%1,%2,%3}, {%4,%5,%6,%7}, {%8,%9}, {%0,%1,%2,%3};"
        : "+f"(d[0]), "+f"(d[1]), "+f"(d[2]), "+f"(d[3])
        : "r"(a[0]), "r"(a[1]), "r"(a[2]), "r"(a[3]), "r"(b[0]), "r"(b[1]));
}
__device__ __forceinline__ void cpa16(uint32_t dst, const void* src) {
    asm volatile("cp.async.cg.shared.global [%0], [%1], 16;" :: "r"(dst), "l"(src));
}
#define CP_COMMIT() asm volatile("cp.async.commit_group;" ::: "memory")
#define CP_WAIT(n)  asm volatile("cp.async.wait_group " #n ";" ::: "memory")

// ---------------- Kernel 0a: build 5 shifted fp16 copies of x ----------------
__global__ void prep_x_kernel(const float* __restrict__ x) {
    __shared__ __align__(16) float xs[2052];
    const int seg = blockIdx.x, i = blockIdx.y, b = blockIdx.z;
    const int t0 = seg * 2048;
    const int tid = threadIdx.x;
    const float* xr = x + ((size_t)b * EDIM + i) * LDIM + t0;

    const float4* xv = reinterpret_cast<const float4*>(xr);
    reinterpret_cast<float4*>(xs)[2 * tid]     = xv[2 * tid];
    reinterpret_cast<float4*>(xs)[2 * tid + 1] = xv[2 * tid + 1];
    if (tid < 4)
        xs[2048 + tid] = (t0 + 2048 + tid < LDIM) ? xr[2048 + tid] : 0.0f;
    __syncthreads();

    #pragma unroll
    for (int k = 0; k < KSZ; k++) {
        uint32_t p[4];
        #pragma unroll
        for (int q = 0; q < 4; q++) {
            __half2 h2 = __floats2half2_rn(xs[tid * 8 + k + 2 * q],
                                           xs[tid * 8 + k + 2 * q + 1]);
            p[q] = *reinterpret_cast<uint32_t*>(&h2);
        }
        __half* dst = g_xh5 + (((size_t)k * BDIM + b) * EDIM + i) * LDIM + t0 + tid * 8;
        *reinterpret_cast<uint4*>(dst) = make_uint4(p[0], p[1], p[2], p[3]);
    }
}

// ---------------- Kernel 0b: weights -> g_wk5[k][e][i] fp16; zero g_s ----------------
__global__ void prep_w_kernel(const float* __restrict__ w) {
    int idx = blockIdx.x * 256 + threadIdx.x;
    if (idx < KSZ * EDIM * EDIM) {
        int k = idx / (EDIM * EDIM);
        int r = idx - k * (EDIM * EDIM);
        int e = r / EDIM, i = r - e * EDIM;
        g_wk5[idx] = __float2half_rn(w[((size_t)e * EDIM + i) * KSZ + k]);
    }
    if (idx < BDIM * LDIM) g_s[idx] = 0.0f;
}

// ---------------- Kernel 1: conv as 5 shifted fp16 GEMMs (mma.sync) — R15-identical ----------------
__global__ void __launch_bounds__(512, 1)
conv_mma_kernel(const float* __restrict__ cb,
                const float* __restrict__ sw) {
    extern __shared__ char smem[];
    const uint32_t sb = smem_u32(smem);
    const int tid = threadIdx.x;
    const int wid = tid >> 5, lid = tid & 31;
    const int b  = blockIdx.z;
    const int te = blockIdx.y * NBLK;
    const int tt = blockIdx.x * MBLK;

    float acc[2][8][4];
    #pragma unroll
    for (int i = 0; i < 2; i++)
        #pragma unroll
        for (int j = 0; j < 8; j++)
            #pragma unroll
            for (int q = 0; q < 4; q++)
                acc[i][j][q] = 0.0f;

    auto stage = [&](int c) {
        const int i0 = c * IBLK;
        const uint32_t bufb = sb + (c & 1) * BUF_B;
        // A: 5k x 16i x 16 t-vec16B = 1280 ops
        for (int o = tid; o < KSZ * IBLK * 16; o += 512) {
            int k = o >> 8;
            int r = o & 255;
            int i = r >> 4;
            int tc = r & 15;
            const __half* src = g_xh5 + (((size_t)k * BDIM + b) * EDIM + (i0 + i)) * LDIM
                              + tt + tc * 8;
            cpa16(bufb + k * A_TILE + i * A_STRIDE_B + tc * 16, src);
        }
        // B: 5k x 256e x 2 half-rows = 2560 ops
        for (int o = tid; o < KSZ * NBLK * 2; o += 512) {
            int k = o >> 9;
            int r = o & 511;
            int e = r >> 1;
            int h = r & 1;
            const __half* src = g_wk5 + ((size_t)k * EDIM + (te + e)) * EDIM + i0 + h * 8;
            cpa16(bufb + A_SZ + k * B_TILE + e * B_STRIDE_B + h * 16, src);
        }
    };

    const int wm = (wid & 3) * 32;     // warp m (t) offset
    const int wn = (wid >> 2) * 64;    // warp n (e) offset

    // A trans-ldmatrix lane addressing on [i][t] storage
    const uint32_t i_rowA = (uint32_t)((lid & 7) + ((lid & 16) ? 8 : 0));
    const uint32_t t_offA = (uint32_t)((lid & 8) ? 8 : 0);
    const uint32_t aoff   = i_rowA * A_STRIDE_B + (uint32_t)(wm + t_offA) * 2;
    // B non-trans, rows e of 16 i
    const int b_q   = lid >> 3;
    const int b_row = wn + ((b_q & 2) ? 8 : 0) + (lid & 7);
    const uint32_t b_cb = (uint32_t)((b_q & 1) ? 16 : 0);

    stage(0);
    CP_COMMIT();

    for (int c = 0; c < NCHI; c++) {
        if (c + 1 < NCHI) {
            stage(c + 1);
            CP_COMMIT();
            CP_WAIT(1);
        } else {
            CP_WAIT(0);
        }
        __syncthreads();

        const uint32_t bufb  = sb + (c & 1) * BUF_B;
        const uint32_t Bbase = bufb + A_SZ;
        #pragma unroll
        for (int k = 0; k < KSZ; k++) {
            const uint32_t Ak = bufb + k * A_TILE;
            const uint32_t Bk = Bbase + k * B_TILE;
            uint32_t a0[4], a1[4];
            ldsm_x4_t(Ak + aoff, a0);
            ldsm_x4_t(Ak + aoff + 32, a1);     // +16 t
            #pragma unroll
            for (int ng = 0; ng < 4; ng++) {
                uint32_t bb[4];
                ldsm_x4(Bk + (uint32_t)(b_row + ng * 16) * B_STRIDE_B + b_cb, bb);
                mma_fp16(acc[0][2 * ng],     a0, &bb[0]);
                mma_fp16(acc[0][2 * ng + 1], a0, &bb[2]);
                mma_fp16(acc[1][2 * ng],     a1, &bb[0]);
                mma_fp16(acc[1][2 * ng + 1], a1, &bb[2]);
            }
        }
        __syncthreads();
    }

    // ---- epilogue: bias + store y (fp32) + fused score projection ----
    const int r = lid & 3, qr = lid >> 2;
    #pragma unroll
    for (int mt = 0; mt < 2; mt++) {
        const int tg0 = tt + wm + mt * 16 + qr;   // and tg0 + 8
        float s0 = 0.0f, s1 = 0.0f;
        #pragma unroll
        for (int n8 = 0; n8 < 8; n8++) {
            const int e0 = te + wn + n8 * 8 + r * 2;
            const float cb0 = __ldg(&cb[e0]), cb1 = __ldg(&cb[e0 + 1]);
            const float sw0 = __ldg(&sw[e0]), sw1 = __ldg(&sw[e0 + 1]);
            float c0 = acc[mt][n8][0] + cb0;
            float c1 = acc[mt][n8][1] + cb1;
            float c2 = acc[mt][n8][2] + cb0;
            float c3 = acc[mt][n8][3] + cb1;
            float* y0 = g_y + ((size_t)b * EDIM + e0) * LDIM;
            float* y1 = y0 + LDIM;
            if (tg0 < LC)     { y0[tg0] = c0;     y1[tg0] = c1; }
            if (tg0 + 8 < LC) { y0[tg0 + 8] = c2; y1[tg0 + 8] = c3; }
            s0 += c0 * sw0 + c1 * sw1;
            s1 += c2 * sw0 + c3 * sw1;
        }
        s0 += __shfl_xor_sync(0xFFFFFFFF, s0, 1);
        s0 += __shfl_xor_sync(0xFFFFFFFF, s0, 2);
        s1 += __shfl_xor_sync(0xFFFFFFFF, s1, 1);
        s1 += __shfl_xor_sync(0xFFFFFFFF, s1, 2);
        if (r == 0) {
            if (tg0 < LC)     atomicAdd(&g_s[b * LDIM + tg0], s0);
            if (tg0 + 8 < LC) atomicAdd(&g_s[b * LDIM + tg0 + 8], s1);
        }
    }
}

// ---------------- Kernel 2: per-(b,t) softmax over widths {1,2,3} ----------------
__global__ void att_kernel() {
    const int b = blockIdx.y;
    const int t = blockIdx.x * 256 + threadIdx.x;
    const float* s = g_s + b * LDIM;

    float sc1 = (t < LC) ? s[t] : 0.0f;
    int n2 = t >> 1;
    float sc2 = (t < LC) ? 0.5f * (s[2 * n2] + s[2 * n2 + 1]) : 0.0f;
    float sc3 = 0.0f;
    int m = t / 3;
    if (t < 8190) {
        sc3 = (s[3 * m] + s[3 * m + 1] + s[3 * m + 2]) * (1.0f / 3.0f);
    }
    float mx = fmaxf(sc1, fmaxf(sc2, sc3));
    float e1 = expf(sc1 - mx), e2 = expf(sc2 - mx), e3 = expf(sc3 - mx);
    float inv = 1.0f / (e1 + e2 + e3);
    g_a1[b * LDIM + t] = e1 * inv;
    g_a2[b * LDIM + t] = e2 * inv;
}

// ---------------- Kernel 3: mix widths + downsample by 2 (fp32 y, fewer L1 wavefronts) ----------------
__device__ __forceinline__ float v3_at(const float* __restrict__ y, int t) {
    if (t >= 8190) return 0.0f;
    int i0 = 3 * (t / 3);                       // <= 8187, in-bounds
    float s0 = y[i0];
    float s1 = (i0 + 1 < LC) ? y[i0 + 1] : 0.0f;
    float s2 = (i0 + 2 < LC) ? y[i0 + 2] : 0.0f;
    return (s0 + s1 + s2) * (1.0f / 3.0f);
}

__global__ void final_kernel(float* __restrict__ out) {
    const int b  = blockIdx.z;
    const int e  = blockIdx.y;
    const int td = blockIdx.x * 256 + threadIdx.x;   // 0..4095
    const float* y = g_y + ((size_t)b * EDIM + e) * LDIM;
    const int t0 = 2 * td, t1 = t0 + 1;

    float2 yp = *reinterpret_cast<const float2*>(y + t0);   // 8B-aligned (t0 even), in-bounds
    float v1_0 = (t0 < LC) ? yp.x : 0.0f;
    float v1_1 = (t1 < LC) ? yp.y : 0.0f;
    float v2   = 0.5f * (v1_0 + v1_1);                       // shared w=2 block (n2 = td)

    float v3_0 = v3_at(y, t0);
    float v3_1 = v3_at(y, t1);

    float2 a1 = *reinterpret_cast<const float2*>(g_a1 + b * LDIM + t0);
    float2 a2 = *reinterpret_cast<const float2*>(g_a2 + b * LDIM + t0);
    float a3_0 = 1.0f - a1.x - a2.x;
    float a3_1 = 1.0f - a1.y - a2.y;

    float z0 = v1_0 * a1.x + v2 * a2.x + v3_0 * a3_0;
    float z1 = v1_1 * a1.y + v2 * a2.y + v3_1 * a3_1;
    out[((size_t)b * EDIM + e) * TD + td] = 0.5f * (z0 + z1);
}

// ---------------- launch ----------------
extern "C" void kernel_launch(void* const* d_in, const int* in_sizes, int n_in,
                              void* d_out, int out_size) {
    (void)in_sizes; (void)n_in; (void)out_size;
    const float* x  = (const float*)d_in[0];   // [8,512,8192]
    const float* cw = (const float*)d_in[1];   // [512,512,5]
    const float* cb = (const float*)d_in[2];   // [512]
    const float* sw = (const float*)d_in[3];   // [512]
    float* out = (float*)d_out;                // [8,512,4096]

    cudaFuncSetAttribute(conv_mma_kernel,
                         cudaFuncAttributeMaxDynamicSharedMemorySize, SMEM_TOTAL);

    prep_x_kernel<<<dim3(LDIM / 2048, EDIM, BDIM), 256>>>(x);
    prep_w_kernel<<<(KSZ * EDIM * EDIM + 255) / 256, 256>>>(cw);
    conv_mma_kernel<<<dim3(LDIM / MBLK, EDIM / NBLK, BDIM), 512, SMEM_TOTAL>>>(cb, sw);
    att_kernel<<<dim3(LDIM / 256, BDIM), 256>>>();
    final_kernel<<<dim3(TD / 256, EDIM, BDIM), 256>>>(out);
}